// round 1
// baseline (speedup 1.0000x reference)
#include <cuda_runtime.h>
#include <cstdint>

// Problem constants (fixed by the dataset)
#define N_ROWS  (64 * 2048)   // 131072
#define DDIM    128
#define KCODES  1024

// Output layout (fp32, concatenated in reference return order)
#define Q_OFF    ((size_t)0)
#define IND_OFF  ((size_t)16777216)
#define EMB_OFF  ((size_t)16908288)
#define NCS_OFF  ((size_t)17039360)
#define NEA_OFF  ((size_t)17040384)

#define DECAYF   0.99f
#define OMDF     0.01f        // float(1.0 - 0.99)
#define EPSF     1e-5f
#define KEPSF    0.01024f     // float(1024 * 1e-5)

// Scratch (no allocation allowed -> __device__ globals)
__device__ float g_counts[KCODES];
__device__ float g_embed_sum[KCODES * DDIM];
__device__ float g_total;
__device__ float g_ee[KCODES];
__device__ int   g_idx[N_ROWS];

// ---------------------------------------------------------------------------
// Zero scratch accumulators
__global__ void k_zero() {
    int t = blockIdx.x * blockDim.x + threadIdx.x;
    if (t < KCODES * DDIM) g_embed_sum[t] = 0.0f;
    if (t < KCODES) g_counts[t] = 0.0f;
    if (t == 0) g_total = 0.0f;
}

// ---------------------------------------------------------------------------
// Per-code squared norms: g_ee[k] = sum_d embed[k][d]^2
__global__ void k_ee(const float* __restrict__ embed) {
    int k = blockIdx.x;
    int t = threadIdx.x;  // 128
    float v = embed[(size_t)k * DDIM + t];
    v *= v;
    __shared__ float s[4];
    #pragma unroll
    for (int o = 16; o > 0; o >>= 1) v += __shfl_down_sync(0xffffffffu, v, o);
    if ((t & 31) == 0) s[t >> 5] = v;
    __syncthreads();
    if (t == 0) g_ee[k] = s[0] + s[1] + s[2] + s[3];
}

// ---------------------------------------------------------------------------
// Fused: score GEMM + argmax + write quantized + embed_ind.
// Tile: 64 rows x 64 codes per block, 256 threads (16x16), 4x4 register blocking.
__global__ __launch_bounds__(256, 2) void k_argmax(const float* __restrict__ x,
                                                   const float* __restrict__ embed,
                                                   float* __restrict__ out) {
    __shared__ float Xs[64][17];
    __shared__ float Es[64][17];
    __shared__ float xxs[64];
    __shared__ float ees[64];
    __shared__ float redv[64][16];
    __shared__ int   redi[64][16];
    __shared__ int   fidx[64];

    const int t   = threadIdx.x;
    const int tx  = t & 15;
    const int ty  = t >> 4;
    const int row0 = blockIdx.x * 64;

    // Pre-pass: row squared norms xx[r] = sum_d x[r][d]^2
    {
        int r = t >> 2, seg = t & 3;
        const float4* xp = (const float4*)(x + (size_t)(row0 + r) * DDIM + seg * 32);
        float s = 0.0f;
        #pragma unroll
        for (int i = 0; i < 8; i++) {
            float4 v = xp[i];
            s += v.x * v.x + v.y * v.y + v.z * v.z + v.w * v.w;
        }
        s += __shfl_down_sync(0xffffffffu, s, 1);
        s += __shfl_down_sync(0xffffffffu, s, 2);
        if (seg == 0) xxs[r] = s;
    }
    __syncthreads();

    float best[4];
    int   bidx[4];
    #pragma unroll
    for (int i = 0; i < 4; i++) { best[i] = -3.402823466e38f; bidx[i] = 0; }

    for (int kt = 0; kt < KCODES; kt += 64) {
        if (t < 64) ees[t] = g_ee[kt + t];

        float acc[4][4];
        #pragma unroll
        for (int i = 0; i < 4; i++)
            #pragma unroll
            for (int j = 0; j < 4; j++) acc[i][j] = 0.0f;

        for (int d0 = 0; d0 < DDIM; d0 += 16) {
            __syncthreads();
            {
                int r = t >> 2, ds = (t & 3) * 4;
                float4 xv = *(const float4*)(x + (size_t)(row0 + r) * DDIM + d0 + ds);
                Xs[r][ds + 0] = xv.x; Xs[r][ds + 1] = xv.y;
                Xs[r][ds + 2] = xv.z; Xs[r][ds + 3] = xv.w;
                float4 ev = *(const float4*)(embed + (size_t)(kt + r) * DDIM + d0 + ds);
                Es[r][ds + 0] = ev.x; Es[r][ds + 1] = ev.y;
                Es[r][ds + 2] = ev.z; Es[r][ds + 3] = ev.w;
            }
            __syncthreads();
            #pragma unroll
            for (int d = 0; d < 16; d++) {
                float a[4], b[4];
                #pragma unroll
                for (int i = 0; i < 4; i++) a[i] = Xs[ty * 4 + i][d];
                #pragma unroll
                for (int j = 0; j < 4; j++) b[j] = Es[tx * 4 + j][d];
                #pragma unroll
                for (int i = 0; i < 4; i++)
                    #pragma unroll
                    for (int j = 0; j < 4; j++)
                        acc[i][j] = fmaf(a[i], b[j], acc[i][j]);
            }
        }

        // Compare against running best with the reference's dist formula.
        #pragma unroll
        for (int i = 0; i < 4; i++) {
            float nxx = -xxs[ty * 4 + i];
            #pragma unroll
            for (int j = 0; j < 4; j++) {
                int k = kt + tx * 4 + j;
                float dist = (nxx + 2.0f * acc[i][j]) - ees[tx * 4 + j];
                if (dist > best[i]) { best[i] = dist; bidx[i] = k; }
            }
        }
        __syncthreads();
    }

    // Cross-thread (tx) reduction per row; ties -> lowest index (jnp.argmax).
    #pragma unroll
    for (int i = 0; i < 4; i++) {
        redv[ty * 4 + i][tx] = best[i];
        redi[ty * 4 + i][tx] = bidx[i];
    }
    __syncthreads();
    if (t < 64) {
        float bv = redv[t][0];
        int   bi = redi[t][0];
        #pragma unroll
        for (int j = 1; j < 16; j++) {
            float v = redv[t][j];
            int   id = redi[t][j];
            if (v > bv || (v == bv && id < bi)) { bv = v; bi = id; }
        }
        fidx[t] = bi;
        int r = row0 + t;
        g_idx[r] = bi;
        out[IND_OFF + (size_t)r] = (float)bi;
    }
    __syncthreads();

    // quantized = embed[idx] (coalesced float4 gather-copy)
    for (int v = t; v < 64 * 32; v += 256) {
        int r = v >> 5, seg = v & 31;
        const float4* ep = (const float4*)(embed + (size_t)fidx[r] * DDIM);
        ((float4*)out)[(size_t)(row0 + r) * 32 + seg] = ep[seg];
    }
}

// ---------------------------------------------------------------------------
// Scatter-add: counts[idx] += 1, embed_sum[idx] += x[row]
__global__ void k_scatter(const float* __restrict__ x) {
    int row = blockIdx.x;
    int d   = threadIdx.x;  // 128
    int idx = g_idx[row];
    atomicAdd(&g_embed_sum[(size_t)idx * DDIM + d], x[(size_t)row * DDIM + d]);
    if (d == 0) atomicAdd(&g_counts[idx], 1.0f);
}

// ---------------------------------------------------------------------------
// new_cluster_size + total sum (single block of 1024 threads)
__global__ void k_c1(const float* __restrict__ cs, float* __restrict__ out) {
    int i = threadIdx.x;  // 1024
    float ncs = cs[i] * DECAYF + OMDF * g_counts[i];
    out[NCS_OFF + (size_t)i] = ncs;

    float v = ncs;
    #pragma unroll
    for (int o = 16; o > 0; o >>= 1) v += __shfl_down_sync(0xffffffffu, v, o);
    __shared__ float s[32];
    if ((i & 31) == 0) s[i >> 5] = v;
    __syncthreads();
    if (i < 32) {
        float w = s[i];
        #pragma unroll
        for (int o = 16; o > 0; o >>= 1) w += __shfl_down_sync(0xffffffffu, w, o);
        if (i == 0) g_total = w;
    }
}

// ---------------------------------------------------------------------------
// new_embed_avg + new_embed
__global__ void k_c2(const float* __restrict__ ea, float* __restrict__ out) {
    int k = blockIdx.x;
    int d = threadIdx.x;  // 128
    size_t off = (size_t)k * DDIM + d;
    float nea = ea[off] * DECAYF + OMDF * g_embed_sum[off];
    out[NEA_OFF + off] = nea;
    float total = g_total;
    float ncs   = out[NCS_OFF + (size_t)k];
    float sm    = (ncs + EPSF) / (total + KEPSF) * total;
    out[EMB_OFF + off] = nea / sm;
}

// ---------------------------------------------------------------------------
extern "C" void kernel_launch(void* const* d_in, const int* in_sizes, int n_in,
                              void* d_out, int out_size) {
    const float* x  = (const float*)d_in[0];
    const float* e  = (const float*)d_in[1];
    const float* ea = (const float*)d_in[2];
    const float* cs = (const float*)d_in[3];
    float* out = (float*)d_out;

    k_zero<<<(KCODES * DDIM + 255) / 256, 256>>>();
    k_ee<<<KCODES, 128>>>(e);
    k_argmax<<<N_ROWS / 64, 256>>>(x, e, out);
    k_scatter<<<N_ROWS, 128>>>(x);
    k_c1<<<1, 1024>>>(cs, out);
    k_c2<<<KCODES, 128>>>(ea, out);
}

// round 3
// speedup vs baseline: 1.4449x; 1.4449x over previous
#include <cuda_runtime.h>
#include <cuda_bf16.h>
#include <cstdint>
#include <float.h>

// Problem constants
#define N_ROWS  (64 * 2048)   // 131072
#define DDIM    128
#define KCODES  1024

// Output layout (fp32, concatenated in reference return order)
#define Q_OFF    ((size_t)0)
#define IND_OFF  ((size_t)16777216)
#define EMB_OFF  ((size_t)16908288)
#define NCS_OFF  ((size_t)17039360)
#define NEA_OFF  ((size_t)17040384)

#define DECAYF   0.99f
#define OMDF     0.01f
#define EPSF     1e-5f
#define KEPSF    0.01024f

#define SCREEN_T 0.6f
#define CAND_CAP 64

// ---------------------------------------------------------------------------
// Scratch (__device__ globals; no allocation allowed)
__device__ float    g_counts[KCODES];
__device__ float    g_embed_sum[KCODES * DDIM];
__device__ float    g_total;
__device__ float    g_ee[KCODES];
__device__ float    g_xx[N_ROWS];
__device__ int      g_idx[N_ROWS];
__device__ uint32_t g_X16[(size_t)N_ROWS * 64];  // bf16x2-packed X rows (32 MB)
__device__ uint4    g_E16[KCODES * 16];          // bf16 E, XOR-swizzled 16B units (256 KB)

// ---------------------------------------------------------------------------
__global__ void k_zero() {
    int t = blockIdx.x * blockDim.x + threadIdx.x;
    if (t < KCODES * DDIM) g_embed_sum[t] = 0.0f;
    if (t < KCODES) g_counts[t] = 0.0f;
    if (t == 0) g_total = 0.0f;
}

// Per-code squared norms
__global__ void k_ee(const float* __restrict__ embed) {
    int k = blockIdx.x;
    int t = threadIdx.x;  // 128
    float v = embed[(size_t)k * DDIM + t];
    v *= v;
    __shared__ float s[4];
    #pragma unroll
    for (int o = 16; o > 0; o >>= 1) v += __shfl_down_sync(0xffffffffu, v, o);
    if ((t & 31) == 0) s[t >> 5] = v;
    __syncthreads();
    if (t == 0) g_ee[k] = s[0] + s[1] + s[2] + s[3];
}

// Pack X rows to bf16x2 + compute row squared norms. 4 rows/block, 64 thr/row.
__global__ void k_packX(const float* __restrict__ x) {
    int tid = threadIdx.x;           // 256
    int r   = blockIdx.x * 4 + (tid >> 6);
    int i   = tid & 63;
    float2 v = ((const float2*)(x + (size_t)r * DDIM))[i];
    __nv_bfloat162 b = __float22bfloat162_rn(v);
    g_X16[(size_t)r * 64 + i] = *(uint32_t*)&b;
    float ss = v.x * v.x + v.y * v.y;
    #pragma unroll
    for (int o = 16; o > 0; o >>= 1) ss += __shfl_down_sync(0xffffffffu, ss, o);
    __shared__ float s[8];
    if ((tid & 31) == 0) s[tid >> 5] = ss;
    __syncthreads();
    if ((tid & 63) == 0) g_xx[r] = s[(tid >> 5)] + s[(tid >> 5) + 1];
}

// Pack E into bf16 with per-row XOR swizzle on 16B units: unit u of row r is
// stored at u ^ (r & 7). Makes ldmatrix (8 rows, 256B stride) conflict-free.
__global__ void k_packE(const float* __restrict__ embed) {
    int idx = blockIdx.x * blockDim.x + threadIdx.x;  // 16384 = 1024 rows * 16 units
    int r = idx >> 4;
    int u = idx & 15;
    const float* src = embed + (size_t)r * DDIM + u * 8;
    float4 a = ((const float4*)src)[0];
    float4 b = ((const float4*)src)[1];
    __nv_bfloat162 p0 = __float22bfloat162_rn(make_float2(a.x, a.y));
    __nv_bfloat162 p1 = __float22bfloat162_rn(make_float2(a.z, a.w));
    __nv_bfloat162 p2 = __float22bfloat162_rn(make_float2(b.x, b.y));
    __nv_bfloat162 p3 = __float22bfloat162_rn(make_float2(b.z, b.w));
    uint4 out;
    out.x = *(uint32_t*)&p0; out.y = *(uint32_t*)&p1;
    out.z = *(uint32_t*)&p2; out.w = *(uint32_t*)&p3;
    g_E16[r * 16 + (u ^ (r & 7))] = out;
}

// ---------------------------------------------------------------------------
__device__ __forceinline__ uint32_t smem_u32(const void* p) {
    uint32_t a;
    asm("{ .reg .u64 t; cvta.to.shared.u64 t, %1; cvt.u32.u64 %0, t; }" : "=r"(a) : "l"(p));
    return a;
}

// ---------------------------------------------------------------------------
// HMMA screening + exact fp32 rescore. CTA = 128 threads (4 warps),
// each warp owns 32 rows (A in registers), sweeps all 1024 codes.
__global__ __launch_bounds__(128, 4) void k_score(const float* __restrict__ x,
                                                  const float* __restrict__ embed,
                                                  float* __restrict__ out) {
    __shared__ __align__(16) uint4 smE[1024];       // 16 KB: 64 codes x 128 bf16
    __shared__ float     sEE[64];
    __shared__ uint16_t  sCand[128 * CAND_CAP];     // 16 KB
    __shared__ uint32_t  sCnt[128];
    __shared__ int       fidx[128];

    const int tid  = threadIdx.x;
    const int wid  = tid >> 5;
    const int lane = tid & 31;
    const int g    = lane >> 2;       // row group within m16 tile
    const int tig  = lane & 3;        // col/thread-in-group
    const int rbase = blockIdx.x * 128 + wid * 32;

    sCnt[tid] = 0;

    // Load A fragments: 2 row-tiles x 8 k-steps x 4 regs (this warp's 32 rows).
    uint32_t afr[2][8][4];
    #pragma unroll
    for (int t2 = 0; t2 < 2; t2++) {
        const size_t rA = (size_t)(rbase + t2 * 16 + g) * 64;
        const size_t rB = rA + 8 * 64;
        #pragma unroll
        for (int ks = 0; ks < 8; ks++) {
            afr[t2][ks][0] = g_X16[rA + 8 * ks + tig];
            afr[t2][ks][1] = g_X16[rB + 8 * ks + tig];
            afr[t2][ks][2] = g_X16[rA + 8 * ks + 4 + tig];
            afr[t2][ks][3] = g_X16[rB + 8 * ks + 4 + tig];
        }
    }

    float rmax[4];
    #pragma unroll
    for (int i = 0; i < 4; i++) rmax[i] = -FLT_MAX;

    const uint32_t smEa = smem_u32(smE);
    const int lsel  = lane & 15;
    const int mrow8 = lsel & 7;       // row within 8-code group for ldmatrix addr
    const int half  = lsel >> 3;      // which 8x8 (k0-7 vs k8-15)

    for (int c = 0; c < 16; c++) {    // 16 chunks of 64 codes
        __syncthreads();
        {
            const uint4* ep = g_E16 + c * 1024;
            #pragma unroll
            for (int i = 0; i < 8; i++) smE[tid + i * 128] = ep[tid + i * 128];
            if (tid < 64) sEE[tid] = g_ee[c * 64 + tid];
        }
        __syncthreads();

        #pragma unroll
        for (int grp = 0; grp < 8; grp++) {
            const int mrow = grp * 8 + mrow8;
            const uint32_t rowaddr = smEa + (mrow << 8);
            const int sw = mrow & 7;

            float acc[2][4];
            #pragma unroll
            for (int t2 = 0; t2 < 2; t2++)
                #pragma unroll
                for (int i = 0; i < 4; i++) acc[t2][i] = 0.0f;

            #pragma unroll
            for (int ks = 0; ks < 8; ks++) {
                uint32_t b0, b1;
                const uint32_t addr = rowaddr + (((2 * ks + half) ^ sw) << 4);
                asm volatile("ldmatrix.sync.aligned.m8n8.x2.shared.b16 {%0,%1}, [%2];"
                             : "=r"(b0), "=r"(b1) : "r"(addr));
                #pragma unroll
                for (int t2 = 0; t2 < 2; t2++) {
                    asm volatile(
                        "mma.sync.aligned.m16n8k16.row.col.f32.bf16.bf16.f32 "
                        "{%0,%1,%2,%3}, {%4,%5,%6,%7}, {%8,%9}, {%0,%1,%2,%3};"
                        : "+f"(acc[t2][0]), "+f"(acc[t2][1]),
                          "+f"(acc[t2][2]), "+f"(acc[t2][3])
                        : "r"(afr[t2][ks][0]), "r"(afr[t2][ks][1]),
                          "r"(afr[t2][ks][2]), "r"(afr[t2][ks][3]),
                          "r"(b0), "r"(b1));
                }
            }

            // Screening: dist-without-xx = 2*dot - ee (xx is row-constant).
            const int code0 = c * 64 + grp * 8 + 2 * tig;
            const float ee0 = sEE[grp * 8 + 2 * tig];
            const float ee1 = sEE[grp * 8 + 2 * tig + 1];
            #pragma unroll
            for (int t2 = 0; t2 < 2; t2++) {
                #pragma unroll
                for (int h = 0; h < 2; h++) {   // h=0: row g, h=1: row g+8
                    const int lr = wid * 32 + t2 * 16 + h * 8 + g;  // CTA-local row
                    float m = rmax[t2 * 2 + h];
                    const float s0 = 2.0f * acc[t2][2 * h] - ee0;
                    if (s0 > m) m = s0;
                    if (s0 >= m - SCREEN_T) {
                        uint32_t n = atomicAdd(&sCnt[lr], 1u);
                        if (n < CAND_CAP) sCand[lr * CAND_CAP + n] = (uint16_t)code0;
                    }
                    const float s1 = 2.0f * acc[t2][2 * h + 1] - ee1;
                    if (s1 > m) m = s1;
                    if (s1 >= m - SCREEN_T) {
                        uint32_t n = atomicAdd(&sCnt[lr], 1u);
                        if (n < CAND_CAP) sCand[lr * CAND_CAP + n] = (uint16_t)(code0 + 1);
                    }
                    rmax[t2 * 2 + h] = m;
                }
            }
        }

        // Tighten running max across the 4 lanes sharing each row.
        #pragma unroll
        for (int i = 0; i < 4; i++) {
            float v = rmax[i];
            v = fmaxf(v, __shfl_xor_sync(0xffffffffu, v, 1));
            v = fmaxf(v, __shfl_xor_sync(0xffffffffu, v, 2));
            rmax[i] = v;
        }
    }
    __syncthreads();

    // Exact fp32 rescore: one thread per row.
    {
        const int lr  = tid;
        const int row = blockIdx.x * 128 + lr;
        const float xx = g_xx[row];
        const uint32_t cnt = sCnt[lr];
        const float4* xr = (const float4*)(x + (size_t)row * DDIM);
        float bestv = -FLT_MAX;
        int   bestk = 0;
        const int nIt = (cnt <= CAND_CAP) ? (int)cnt : KCODES;
        for (int j = 0; j < nIt; j++) {
            const int k = (cnt <= CAND_CAP) ? (int)sCand[lr * CAND_CAP + j] : j;
            const float4* er = (const float4*)(embed + (size_t)k * DDIM);
            float a0 = 0.f, a1 = 0.f, a2 = 0.f, a3 = 0.f;
            #pragma unroll 8
            for (int i = 0; i < 32; i++) {
                float4 xa = xr[i], ea = er[i];
                a0 = fmaf(xa.x, ea.x, a0);
                a1 = fmaf(xa.y, ea.y, a1);
                a2 = fmaf(xa.z, ea.z, a2);
                a3 = fmaf(xa.w, ea.w, a3);
            }
            const float dot = (a0 + a1) + (a2 + a3);
            const float dist = (-xx + 2.0f * dot) - g_ee[k];
            if (dist > bestv || (dist == bestv && k < bestk)) { bestv = dist; bestk = k; }
        }
        fidx[lr] = bestk;
        g_idx[row] = bestk;
        out[IND_OFF + (size_t)row] = (float)bestk;
    }
    __syncthreads();

    // quantized = embed[idx] (one warp per row, coalesced float4 copy)
    for (int v = tid; v < 128 * 32; v += 128) {
        const int r = v >> 5, seg = v & 31;
        const float4* ep = (const float4*)(embed + (size_t)fidx[r] * DDIM);
        ((float4*)out)[(size_t)(blockIdx.x * 128 + r) * 32 + seg] = ep[seg];
    }
}

// ---------------------------------------------------------------------------
__global__ void k_scatter(const float* __restrict__ x) {
    int row = blockIdx.x;
    int d   = threadIdx.x;  // 128
    int idx = g_idx[row];
    atomicAdd(&g_embed_sum[(size_t)idx * DDIM + d], x[(size_t)row * DDIM + d]);
    if (d == 0) atomicAdd(&g_counts[idx], 1.0f);
}

__global__ void k_c1(const float* __restrict__ cs, float* __restrict__ out) {
    int i = threadIdx.x;  // 1024
    float ncs = cs[i] * DECAYF + OMDF * g_counts[i];
    out[NCS_OFF + (size_t)i] = ncs;
    float v = ncs;
    #pragma unroll
    for (int o = 16; o > 0; o >>= 1) v += __shfl_down_sync(0xffffffffu, v, o);
    __shared__ float s[32];
    if ((i & 31) == 0) s[i >> 5] = v;
    __syncthreads();
    if (i < 32) {
        float w = s[i];
        #pragma unroll
        for (int o = 16; o > 0; o >>= 1) w += __shfl_down_sync(0xffffffffu, w, o);
        if (i == 0) g_total = w;
    }
}

__global__ void k_c2(const float* __restrict__ ea, float* __restrict__ out) {
    int k = blockIdx.x;
    int d = threadIdx.x;  // 128
    size_t off = (size_t)k * DDIM + d;
    float nea = ea[off] * DECAYF + OMDF * g_embed_sum[off];
    out[NEA_OFF + off] = nea;
    float total = g_total;
    float ncs   = out[NCS_OFF + (size_t)k];
    float sm    = (ncs + EPSF) / (total + KEPSF) * total;
    out[EMB_OFF + off] = nea / sm;
}

// ---------------------------------------------------------------------------
extern "C" void kernel_launch(void* const* d_in, const int* in_sizes, int n_in,
                              void* d_out, int out_size) {
    const float* x  = (const float*)d_in[0];
    const float* e  = (const float*)d_in[1];
    const float* ea = (const float*)d_in[2];
    const float* cs = (const float*)d_in[3];
    float* out = (float*)d_out;

    k_zero<<<(KCODES * DDIM + 255) / 256, 256>>>();
    k_ee<<<KCODES, 128>>>(e);
    k_packX<<<N_ROWS / 4, 256>>>(x);
    k_packE<<<64, 256>>>(e);
    k_score<<<N_ROWS / 128, 128>>>(x, e, out);
    k_scatter<<<N_ROWS, 128>>>(x);
    k_c1<<<1, 1024>>>(cs, out);
    k_c2<<<KCODES, 128>>>(ea, out);
}